// round 4
// baseline (speedup 1.0000x reference)
#include <cuda_runtime.h>
#include <math.h>

#define N       512
#define NBATCH  16
#define NT      8
#define NKX     257            // kx = 0..256 kept (Hermitian symmetry)
#define GPAD    516            // group stride in unpack staging (bank-spread)

// Scratch: row-FFT result, TRANSPOSED + half-spectrum: [b][kx][y], kx<257
__device__ float2 g_rowfft[(size_t)NBATCH * NKX * N];
__device__ float  g_segsum[256];
__device__ float  g_cnt[256];

// ---------------------------------------------------------------------------
// complex helpers
// ---------------------------------------------------------------------------
__device__ __forceinline__ float2 cadd(float2 a, float2 b){ return make_float2(a.x+b.x, a.y+b.y); }
__device__ __forceinline__ float2 csub(float2 a, float2 b){ return make_float2(a.x-b.x, a.y-b.y); }
__device__ __forceinline__ float2 cmul(float2 a, float2 b){ return make_float2(a.x*b.x-a.y*b.y, a.x*b.y+a.y*b.x); }
__device__ __forceinline__ float2 mul_mi(float2 a){ return make_float2(a.y, -a.x); }   // * (-i)

// 8-point DFT, natural order in/out, forward
__device__ __forceinline__ void fft8(float2 v[8]) {
    float2 t0, t1, t2, t3, t3m;
    t0 = cadd(v[0], v[4]); t1 = csub(v[0], v[4]);
    t2 = cadd(v[2], v[6]); t3 = csub(v[2], v[6]);
    float2 E0 = cadd(t0, t2), E2 = csub(t0, t2);
    t3m = mul_mi(t3);
    float2 E1 = cadd(t1, t3m), E3 = csub(t1, t3m);
    t0 = cadd(v[1], v[5]); t1 = csub(v[1], v[5]);
    t2 = cadd(v[3], v[7]); t3 = csub(v[3], v[7]);
    float2 O0 = cadd(t0, t2), O2 = csub(t0, t2);
    t3m = mul_mi(t3);
    float2 O1 = cadd(t1, t3m), O3 = csub(t1, t3m);
    const float C = 0.7071067811865476f;
    float2 O1w = make_float2(C*(O1.x + O1.y), C*(O1.y - O1.x));
    float2 O2w = mul_mi(O2);
    float2 O3w = make_float2(C*(O3.y - O3.x), -C*(O3.x + O3.y));
    v[0] = cadd(E0, O0);  v[4] = csub(E0, O0);
    v[1] = cadd(E1, O1w); v[5] = csub(E1, O1w);
    v[2] = cadd(E2, O2w); v[6] = csub(E2, O2w);
    v[3] = cadd(E3, O3w); v[7] = csub(E3, O3w);
}

// ---------------------------------------------------------------------------
// 512-pt FFT, 64 threads (gt = 0..63), 8 elems/thread, radix-8^3 DIF.
// Input: v[j] = x[gt + 64*j]. Output: thread (m=gt>>3, u=gt&7) holds
// X[64*s + 8*u + m] in v[s].  gre/gim: 512-float staging (per group).
// All groups in the block run lockstep (shared __syncthreads).
// ---------------------------------------------------------------------------
__device__ __forceinline__ void fft512(float2 v[8], int gt,
                                       float* __restrict__ gre, float* __restrict__ gim,
                                       const float* __restrict__ tre, const float* __restrict__ tim) {
    fft8(v);
#pragma unroll
    for (int m = 1; m < 8; m++) {
        int k = gt * m;
        v[m] = cmul(v[m], make_float2(tre[k], tim[k]));
    }
#pragma unroll
    for (int m = 0; m < 8; m++) {
        int idx = m * 64 + (gt ^ (m << 3));
        gre[idx] = v[m].x; gim[idx] = v[m].y;
    }
    __syncthreads();
    {
        int m = gt >> 3, p = gt & 7;
#pragma unroll
        for (int i = 0; i < 8; i++) {
            int idx = m * 64 + p + (((i ^ m) & 7) << 3);
            v[i] = make_float2(gre[idx], gim[idx]);
        }
        fft8(v);
#pragma unroll
        for (int u = 1; u < 8; u++) {
            int k = (p * u) << 3;
            v[u] = cmul(v[u], make_float2(tre[k], tim[k]));
        }
        __syncthreads();
#pragma unroll
        for (int u = 0; u < 8; u++) {
            int idx = m * 64 + (((u ^ m) & 7) << 3) + (p ^ (u & 3));
            gre[idx] = v[u].x; gim[idx] = v[u].y;
        }
    }
    __syncthreads();
    {
        int m = gt >> 3, u = gt & 7;
#pragma unroll
        for (int p = 0; p < 8; p++) {
            int idx = m * 64 + (((u ^ m) & 7) << 3) + (p ^ (u & 3));
            v[p] = make_float2(gre[idx], gim[idx]);
        }
        fft8(v);
    }
}

// ---------------------------------------------------------------------------
// K1: mean over T + row FFT with REAL-PAIR PACKING (2 rows per complex FFT)
// 512 threads = 8 FFT groups of 64; block covers 16 rows.
// grid = NBATCH * 32 blocks.
// ---------------------------------------------------------------------------
__global__ void __launch_bounds__(512) kMeanRowFFT(const float* __restrict__ in) {
    const int tid = threadIdx.x;
    const int r   = tid >> 6;          // packed-FFT group (0..7) -> rows 2r,2r+1
    const int gt  = tid & 63;
    const int b   = blockIdx.x >> 5;
    const int y0  = (blockIdx.x & 31) << 4;   // 16 rows per block

    __shared__ float sre[8 * GPAD];
    __shared__ float sim[8 * GPAD];
    __shared__ float tre[512];
    __shared__ float tim[512];

    {
        float s, c;
        sincosf(-6.283185307179586f * (float)tid / 512.0f, &s, &c);
        tre[tid] = c; tim[tid] = s;
    }
    if (blockIdx.x == 0 && tid < 256) { g_segsum[tid] = 0.0f; g_cnt[tid] = 0.0f; }

    // mean over T: v[j] = mean_t rowA[gt+64j] + i * mean_t rowB[gt+64j]
    float2 v[8];
    const float* baseA = in + (((size_t)b * NT) * N + (y0 + 2 * r)) * N + gt;
#pragma unroll
    for (int j = 0; j < 8; j++) {
        float sa = 0.0f, sb = 0.0f;
#pragma unroll
        for (int t = 0; t < NT; t++) {
            const float* p = baseA + (size_t)t * N * N + (j << 6);
            sa += p[0];
            sb += p[N];
        }
        v[j] = make_float2(sa * 0.125f, sb * 0.125f);
    }
    __syncthreads();   // twiddle table ready

    float* gre = sre + r * GPAD;
    float* gim = sim + r * GPAD;
    fft512(v, gt, gre, gim, tre, tim);

    __syncthreads();   // all stage-C reads done; reuse staging for natural order
    {
        int m = gt >> 3, u = gt & 7;
#pragma unroll
        for (int s = 0; s < 8; s++) {
            int n = (s << 6) + (u << 3) + m;
            gre[n] = v[s].x; gim[n] = v[s].y;
        }
    }
    __syncthreads();

    // Hermitian unpack + transposed global write (half-spectrum)
    // thread tid -> (kx_i = tid>>4, y_i = tid&15); loop kx = kx_i + 32*c
    {
        const int y_i  = tid & 15;
        const int kx_i = tid >> 4;
        const int rg   = y_i >> 1;          // source group
        const int isB  = y_i & 1;           // 0: row 2rg (A), 1: row 2rg+1 (B)
        const float* zre = sre + rg * GPAD;
        const float* zim = sim + rg * GPAD;
        float2* outp = g_rowfft + (size_t)b * NKX * N + (y0 + y_i);
#pragma unroll
        for (int c = 0; c < 9; c++) {
            int kx = kx_i + (c << 5);
            if (kx <= 256) {
                int km = (512 - kx) & 511;
                float x1 = zre[kx], y1 = zim[kx];
                float x2 = zre[km], y2 = zim[km];
                float2 o;
                if (!isB) o = make_float2(0.5f * (x1 + x2), 0.5f * (y1 - y2));
                else      o = make_float2(0.5f * (y1 + y2), -0.5f * (x1 - x2));
                outp[(size_t)kx * N] = o;
            }
        }
    }
}

// ---------------------------------------------------------------------------
// K2: column FFT per (kx, batch-quad). grid = (257, 4), 256 threads.
// Each of 4 groups does ONE batch FFT; |F|^2 binned radially (Hermitian wt).
// ---------------------------------------------------------------------------
__global__ void __launch_bounds__(256) kColFFTPower() {
    const int tid = threadIdx.x;
    const int g   = tid >> 6;          // group 0..3
    const int gt  = tid & 63;
    const int kx  = blockIdx.x;        // 0..256
    const int b   = (blockIdx.y << 2) + g;

    __shared__ float sre[4 * 512];
    __shared__ float sim[4 * 512];
    __shared__ float tre[512];
    __shared__ float tim[512];
    __shared__ float bins[256];
    __shared__ float cbin[256];

    {
        float s, c;
        sincosf(-6.283185307179586f * (float)tid / 512.0f, &s, &c);
        tre[tid] = c; tim[tid] = s;
        sincosf(-6.283185307179586f * (float)(tid + 256) / 512.0f, &s, &c);
        tre[tid + 256] = c; tim[tid + 256] = s;
        bins[tid] = 0.0f; cbin[tid] = 0.0f;
    }
    __syncthreads();

    const float2* col = g_rowfft + ((size_t)b * NKX + kx) * N;
    float2 v[8];
#pragma unroll
    for (int j = 0; j < 8; j++) v[j] = col[gt + (j << 6)];

    fft512(v, gt, sre + g * 512, sim + g * 512, tre, tim);

    // radial binning: thread (m,u) owns ky = 64s+8u+m
    {
        const float w    = (kx == 0 || kx == 256) ? 1.0f : 2.0f;
        const float fdx2 = (float)((kx - 256) * (kx - 256));
        const bool  doCnt = (blockIdx.y == 0) && (g == 0);
        int m = gt >> 3, u = gt & 7;
#pragma unroll
        for (int s = 0; s < 8; s++) {
            int ky = (s << 6) + (u << 3) + m;
            int dy = ky - 256;
            int rr = (int)sqrtf(fdx2 + (float)(dy * dy));
            if (rr >= 1 && rr < 256) {
                atomicAdd(&bins[rr], w * (v[s].x * v[s].x + v[s].y * v[s].y));
                if (doCnt) atomicAdd(&cbin[rr], w);
            }
        }
    }
    __syncthreads();

    if (tid >= 1) {
        if (bins[tid] != 0.0f) atomicAdd(&g_segsum[tid], bins[tid]);
        if (cbin[tid] != 0.0f) atomicAdd(&g_cnt[tid],    cbin[tid]);
    }
}

// ---------------------------------------------------------------------------
// K3: normalization + loss (single block)
// ---------------------------------------------------------------------------
__global__ void __launch_bounds__(256) kFinal(float* __restrict__ out) {
    __shared__ float red[256];
    __shared__ float gsum_s, rsum_s;
    const int tid = threadIdx.x;

    float g = 0.0f, rk = 0.0f;
    if (tid >= 1) {
        float c = g_cnt[tid];
        if (c > 0.0f) g = g_segsum[tid] / (fmaxf(c, 1.0f) * 16.0f);  // B*C
        rk = __powf((float)tid, -5.0f / 3.0f);
    }

    red[tid] = g;
    __syncthreads();
    for (int s = 128; s > 0; s >>= 1) { if (tid < s) red[tid] += red[tid + s]; __syncthreads(); }
    if (tid == 0) gsum_s = red[0];
    __syncthreads();

    red[tid] = rk;
    __syncthreads();
    for (int s = 128; s > 0; s >>= 1) { if (tid < s) red[tid] += red[tid + s]; __syncthreads(); }
    if (tid == 0) rsum_s = red[0];
    __syncthreads();

    float gn = g  / (gsum_s + 1e-8f);
    float rn = rk / (rsum_s + 1e-8f);
    float d  = (tid >= 1) ? (gn - rn) * (gn - rn) : 0.0f;

    red[tid] = d;
    __syncthreads();
    for (int s = 128; s > 0; s >>= 1) { if (tid < s) red[tid] += red[tid + s]; __syncthreads(); }
    if (tid == 0) out[0] = red[0] / 255.0f;
}

// ---------------------------------------------------------------------------
extern "C" void kernel_launch(void* const* d_in, const int* in_sizes, int n_in,
                              void* d_out, int out_size) {
    const float* in  = (const float*)d_in[0];
    float*       out = (float*)d_out;

    kMeanRowFFT<<<NBATCH * 32, 512>>>(in);
    dim3 g2(NKX, 4);
    kColFFTPower<<<g2, 256>>>();
    kFinal<<<1, 256>>>(out);
}